// round 8
// baseline (speedup 1.0000x reference)
#include <cuda_runtime.h>
#include <cuda_bf16.h>
#include <math.h>
#include <stdint.h>

#define B_    256
#define T_    128
#define NIN   700
#define H_    2048

// ---------------- device scratch ----------------
__device__ float         g_U [(size_t)B_ * T_ * H_];    // 0.5*(x@W+bias)
__device__ __nv_bfloat16 gA0 [(size_t)H_ * H_];         // A^T splits [n][k]
__device__ __nv_bfloat16 gA1 [(size_t)H_ * H_];
__device__ __nv_bfloat16 gA2 [(size_t)H_ * H_];
__device__ __nv_bfloat16 gS  [2][(size_t)B_ * H_];      // spike ping-pong (exact 0/1)

// ---------------- asm helpers (sm_80+ portable) ----------------
__device__ __forceinline__ uint32_t smem_u32(const void* p) {
    uint32_t a;
    asm("{ .reg .u64 t; cvta.to.shared.u64 t, %1; cvt.u32.u64 %0, t; }"
        : "=r"(a) : "l"(p));
    return a;
}
__device__ __forceinline__ void cpa16(uint32_t dst, const void* src) {
    asm volatile("cp.async.cg.shared.global [%0], [%1], 16;"
                 :: "r"(dst), "l"(src) : "memory");
}
#define CP_COMMIT() asm volatile("cp.async.commit_group;" ::: "memory")
#define CP_WAIT2()  asm volatile("cp.async.wait_group 2;" ::: "memory")

__device__ __forceinline__ void ldsm4(uint32_t* r, uint32_t a) {
    asm volatile("ldmatrix.sync.aligned.m8n8.x4.shared.b16 {%0,%1,%2,%3}, [%4];"
                 : "=r"(r[0]), "=r"(r[1]), "=r"(r[2]), "=r"(r[3]) : "r"(a));
}
__device__ __forceinline__ void ldsm2(uint32_t* r, uint32_t a) {
    asm volatile("ldmatrix.sync.aligned.m8n8.x2.shared.b16 {%0,%1}, [%2];"
                 : "=r"(r[0]), "=r"(r[1]) : "r"(a));
}
__device__ __forceinline__ void mma16816(float* c, const uint32_t* a,
                                         const uint32_t* b) {
    asm volatile("mma.sync.aligned.m16n8k16.row.col.f32.bf16.bf16.f32 "
                 "{%0,%1,%2,%3}, {%4,%5,%6,%7}, {%8,%9}, {%0,%1,%2,%3};"
                 : "+f"(c[0]), "+f"(c[1]), "+f"(c[2]), "+f"(c[3])
                 : "r"(a[0]), "r"(a[1]), "r"(a[2]), "r"(a[3]),
                   "r"(b[0]), "r"(b[1]));
}

// ---------------- bf16 3-way exact split ----------------
__device__ __forceinline__ void split3(float v, __nv_bfloat16& b0,
                                       __nv_bfloat16& b1, __nv_bfloat16& b2) {
    b0 = __float2bfloat16(v);
    float f0 = __bfloat162float(b0);
    b1 = __float2bfloat16(v - f0);
    float f1 = __bfloat162float(b1);
    b2 = __float2bfloat16(v - f0 - f1);
}

__global__ void k_split_A(const float* __restrict__ A) {
    __shared__ float tile[32][33];
    int tx = threadIdx.x, ty = threadIdx.y;
    int kbase = blockIdx.y * 32, nbase = blockIdx.x * 32;
    #pragma unroll
    for (int i = 0; i < 32; i += 8)
        tile[ty + i][tx] = A[(size_t)(kbase + ty + i) * H_ + nbase + tx];
    __syncthreads();
    #pragma unroll
    for (int i = 0; i < 32; i += 8) {
        float v = tile[tx][ty + i];
        size_t o = (size_t)(nbase + ty + i) * H_ + kbase + tx;
        __nv_bfloat16 b0, b1, b2; split3(v, b0, b1, b2);
        gA0[o] = b0; gA1[o] = b1; gA2[o] = b2;
    }
}

// ---------------- input GEMM (fp32 SIMT — bit-identical to round 1) --------
__global__ void __launch_bounds__(256) k_input_gemm(
    const float* __restrict__ X, const float* __restrict__ W,
    const float* __restrict__ bias)
{
    constexpr int K = NIN, N = H_;
    constexpr int BM = 128, BN = 128, BK = 8, TM = 8, TN = 8;
    __shared__ float As[BK][BM];
    __shared__ float Bs[BK][BN];

    const int tid = threadIdx.x;
    const int bm = blockIdx.y, bn = blockIdx.x;
    const int aRow = tid >> 1, aCol = (tid & 1) << 2;
    const int bRow = tid >> 5, bCol = (tid & 31) << 2;
    const int tRow = (tid >> 4) << 3, tCol = (tid & 15) << 3;

    const float* Ab = X + (size_t)(bm * BM) * K;
    const float* Bb = W + bn * BN;

    float acc[TM][TN];
    #pragma unroll
    for (int i = 0; i < TM; i++)
        #pragma unroll
        for (int j = 0; j < TN; j++) acc[i][j] = 0.f;

    for (int k0 = 0; k0 < K; k0 += BK) {
        #pragma unroll
        for (int i = 0; i < 4; i++) {
            int kk = k0 + aCol + i;
            As[aCol + i][aRow] = (kk < K) ? Ab[(size_t)aRow * K + kk] : 0.f;
        }
        if (k0 + bRow < K) {
            float4 v = *(const float4*)(Bb + (size_t)(k0 + bRow) * N + bCol);
            Bs[bRow][bCol + 0] = v.x; Bs[bRow][bCol + 1] = v.y;
            Bs[bRow][bCol + 2] = v.z; Bs[bRow][bCol + 3] = v.w;
        } else {
            Bs[bRow][bCol + 0] = 0.f; Bs[bRow][bCol + 1] = 0.f;
            Bs[bRow][bCol + 2] = 0.f; Bs[bRow][bCol + 3] = 0.f;
        }
        __syncthreads();
        #pragma unroll
        for (int k = 0; k < BK; k++) {
            float aF[TM], bF[TN];
            #pragma unroll
            for (int i = 0; i < TM; i++) aF[i] = As[k][tRow + i];
            #pragma unroll
            for (int j = 0; j < TN; j++) bF[j] = Bs[k][tCol + j];
            #pragma unroll
            for (int i = 0; i < TM; i++)
                #pragma unroll
                for (int j = 0; j < TN; j++) acc[i][j] += aF[i] * bF[j];
        }
        __syncthreads();
    }
    const int m0 = bm * BM + tRow, n0 = bn * BN + tCol;
    #pragma unroll
    for (int i = 0; i < TM; i++) {
        size_t row = (size_t)(m0 + i) * N;
        #pragma unroll
        for (int j = 0; j < TN; j++)
            g_U[row + n0 + j] = 0.5f * (acc[i][j] + bias[n0 + j]);
    }
}

// ---------------- frame 0 (spike0 = 0 -> r = 0) ----------------
__global__ void k_frame0(const float* __restrict__ mem_init,
                         float* __restrict__ out_mems,
                         float* __restrict__ out_spikes)
{
    size_t idx = (size_t)blockIdx.x * 256 + threadIdx.x;
    int b = (int)(idx / H_), n = (int)(idx % H_);
    size_t o = ((size_t)b * T_) * H_ + n;
    float u = g_U[o];
    float y = tanhf(u);
    float mem = mem_init[idx] * 0.5f - 0.5f * (1.0f - 0.0f) + y;
    float sp = (mem > 0.5f) ? 1.0f : 0.0f;
    out_mems[o] = mem;
    out_spikes[o] = sp;
    gS[0][idx] = __float2bfloat16(sp);
}

// ==== recurrent frame: 3-term exact bf16 mma, chunked fold =================
// 512 threads, 16 warps (4x4), warp tile 16m x 16n, 4-stage cp.async ring.
// Per-output-element accumulation order is BIT-IDENTICAL to the passing
// round-6 kernel: per BK=32 chunk, tacc=0; chain (kk0,p0)(kk0,p1)(kk0,p2)
// (kk1,p0)(kk1,p1)(kk1,p2); master += tacc in IEEE fp32.
#define SPD 40                          // padded row stride (bf16 elems)
#define FTILE (64 * SPD)                // 2560 elems / 5120 B per tile
#define FR_SMEM_B (4 * 4 * FTILE * 2)   // 81920 B

__global__ void __launch_bounds__(512)
k_frame_mma(float* __restrict__ out_mems, float* __restrict__ out_spikes, int t)
{
    extern __shared__ __align__(16) __nv_bfloat16 smf[];
    const int tid = threadIdx.x;
    const int lane = tid & 31, w = tid >> 5;      // 16 warps
    const int wm = w & 3, wn = w >> 2;            // warp tile 16(m) x 16(n)
    const int l15 = lane & 15;
    const int n0 = blockIdx.x * 64, m0 = blockIdx.y * 64;

    const __nv_bfloat16* Sg = gS[(t + 1) & 1];
    const __nv_bfloat16* Ap[3] = { gA0 + (size_t)n0 * H_,
                                   gA1 + (size_t)n0 * H_,
                                   gA2 + (size_t)n0 * H_ };

    // stage = 4 tiles x 64 rows x 32 elems (1024 x 16B chunks), 2 per thread
    auto load_stage = [&](int buf, int k0) {
        __nv_bfloat16* st = smf + (size_t)buf * 4 * FTILE;
        #pragma unroll
        for (int h = 0; h < 2; h++) {
            int c = tid + h * 512;                // 0..1023
            int tile = c >> 8;                    // 0..3
            int r = (c >> 2) & 63;
            int j = (c & 3) * 8;
            const __nv_bfloat16* src = (tile == 0)
                ? Sg + (size_t)(m0 + r) * H_ + k0 + j
                : Ap[tile - 1] + (size_t)r * H_ + k0 + j;
            cpa16(smem_u32(st + tile * FTILE + r * SPD + j), src);
        }
    };

    float master[2][4];
    #pragma unroll
    for (int b = 0; b < 2; b++)
        #pragma unroll
        for (int c = 0; c < 4; c++) master[b][c] = 0.f;

    load_stage(0, 0);  CP_COMMIT();
    load_stage(1, 32); CP_COMMIT();
    load_stage(2, 64); CP_COMMIT();

    constexpr int NS = H_ / 32;     // 64 stages, BK=32
    for (int s = 0; s < NS; s++) {
        int buf = s & 3;
        CP_WAIT2();
        __syncthreads();
        if (s + 3 < NS) load_stage((s + 3) & 3, (s + 3) * 32);
        CP_COMMIT();

        float tacc[2][4];
        #pragma unroll
        for (int b = 0; b < 2; b++)
            #pragma unroll
            for (int c = 0; c < 4; c++) tacc[b][c] = 0.f;

        uint32_t sb = smem_u32(smf + (size_t)buf * 4 * FTILE);
        #pragma unroll
        for (int kk = 0; kk < 2; kk++) {
            uint32_t af[4];
            {
                int row = wm * 16 + l15;
                ldsm4(af, sb + (uint32_t)((row * SPD + (lane >> 4) * 8) * 2 + kk * 32));
            }
            #pragma unroll
            for (int p = 0; p < 3; p++) {
                uint32_t ab = sb + (uint32_t)((1 + p) * FTILE * 2);
                #pragma unroll
                for (int ni = 0; ni < 2; ni++) {
                    uint32_t bf[2];
                    int row = wn * 16 + ni * 8 + (l15 & 7);
                    ldsm2(bf, ab + (uint32_t)((row * SPD + ((l15 >> 3) & 1) * 8) * 2 + kk * 32));
                    mma16816(tacc[ni], af, bf);
                }
            }
        }
        #pragma unroll
        for (int b = 0; b < 2; b++)
            #pragma unroll
            for (int c = 0; c < 4; c++) master[b][c] += tacc[b][c];
    }

    // fused epilogue — streaming hints keep the A splits resident in L2
    __nv_bfloat16* Sout = gS[t & 1];
    const int gq = lane >> 2, tq = lane & 3;
    #pragma unroll
    for (int ni = 0; ni < 2; ni++)
        #pragma unroll
        for (int h = 0; h < 2; h++)
            #pragma unroll
            for (int e = 0; e < 2; e++) {
                int b = m0 + wm * 16 + gq + h * 8;
                int n = n0 + wn * 16 + ni * 8 + tq * 2 + e;
                size_t o = ((size_t)b * T_ + t) * H_ + n;
                float u = __ldcs(&g_U[o]);
                float sp_prev  = __ldcs(&out_spikes[o - H_]);
                float mem_prev = __ldcs(&out_mems[o - H_]);
                float y = tanhf(0.5f * master[ni][h * 2 + e] + u);
                float mem = mem_prev * 0.5f - 0.5f * (1.0f - sp_prev) + y;
                float sp = (mem > 0.5f) ? 1.0f : 0.0f;
                __stcs(&out_mems[o], mem);
                __stcs(&out_spikes[o], sp);
                Sout[(size_t)b * H_ + n] = __float2bfloat16(sp);
            }
}

// ----------------------------------------------------------------------------
extern "C" void kernel_launch(void* const* d_in, const int* in_sizes, int n_in,
                              void* d_out, int out_size)
{
    const float* x        = (const float*)d_in[0];
    const float* W_in     = (const float*)d_in[1];
    const float* Arec     = (const float*)d_in[2];
    const float* bias     = (const float*)d_in[3];
    const float* mem_init = (const float*)d_in[4];

    float* out        = (float*)d_out;
    float* out_mems   = out;
    float* out_spikes = out + (size_t)B_ * T_ * H_;

    cudaFuncSetAttribute(k_frame_mma,
                         cudaFuncAttributeMaxDynamicSharedMemorySize, FR_SMEM_B);

    { dim3 g(H_ / 32, H_ / 32), b(32, 8); k_split_A<<<g, b>>>(Arec); }
    { dim3 g(H_ / 128, (B_ * T_) / 128); k_input_gemm<<<g, 256>>>(x, W_in, bias); }

    k_frame0<<<(B_ * H_) / 256, 256>>>(mem_init, out_mems, out_spikes);

    dim3 g(H_ / 64, B_ / 64);
    for (int t = 1; t < T_; t++)
        k_frame_mma<<<g, 512, FR_SMEM_B>>>(out_mems, out_spikes, t);
}